// round 16
// baseline (speedup 1.0000x reference)
#include <cuda_runtime.h>
#include <math.h>

#define H 1024
#define V 50257
#define S 4096
#define NT 256
#define NCHAIN 256      // co-resident (2/SM); barriers count these

// ---------------- scratch (__device__ globals) ----------------
__device__ float g_gi[3 * H];
__device__ float g_gh[3 * H];
__device__ float g_h[H];
__device__ float g_vpart[16][H];     // 16 j-chunks of 64 rows
__device__ float g_scores[S];
__device__ float g_ctx[H];           // accumulated via atomicAdd in P4
__device__ unsigned g_cnt = 0;
__device__ unsigned g_gen = 0;

// ---------------- helpers ----------------
__device__ __forceinline__ float warp_sum(float v) {
#pragma unroll
    for (int o = 16; o; o >>= 1) v += __shfl_xor_sync(0xffffffffu, v, o);
    return v;
}

__device__ __forceinline__ void chain_sync() {
    __syncthreads();
    if (threadIdx.x == 0) {
        __threadfence();
        unsigned gen = *(volatile unsigned*)&g_gen;
        if (atomicAdd(&g_cnt, 1u) == NCHAIN - 1) {
            g_cnt = 0;
            __threadfence();
            *(volatile unsigned*)&g_gen = gen + 1;
        } else {
            while (*(volatile unsigned*)&g_gen == gen) { }
        }
        __threadfence();
    }
    __syncthreads();
}

// ================= K1: chain (persistent 256 blocks, 3 barriers) ==============
__global__ void __launch_bounds__(NT, 2)
k_chain(const int* __restrict__ word,
        const float* __restrict__ last_hidden,
        const float* __restrict__ enc,
        const float* __restrict__ emb,
        const float* __restrict__ w_ih,
        const float* __restrict__ w_hh,
        const float* __restrict__ b_ih,
        const float* __restrict__ b_hh,
        const float* __restrict__ attn_w,
        float* __restrict__ dout) {
    // release the PDL secondary immediately: its blocks prefetch out_w into L2
    // while this grid runs; they griddepcontrol.wait before reading our outputs.
    asm volatile("griddepcontrol.launch_dependents;");

    __shared__ float4 sbuf4[512];   // [0..255]: x then h ; [256..511]: h_prev then v
    __shared__ float red[8];
    __shared__ float bcm, bcs;
    __shared__ float w_sh[64];
    float* h_sh = (float*)sbuf4;

    const int t = threadIdx.x;
    const int b = blockIdx.x;
    const int warp = t >> 5, lane = t & 31;
    const int nwarp = NCHAIN * (NT / 32);        // 2048
    const int gw = b * (NT / 32) + warp;

    // ===== P1: gates — 3 rows per warp, loads interleaved (MLP=3)
    {
        const float* x = emb + (long)word[0] * H;
        sbuf4[t]       = reinterpret_cast<const float4*>(x)[t];
        sbuf4[256 + t] = reinterpret_cast<const float4*>(last_hidden)[t];
        __syncthreads();

        // last block zeroes g_ctx for this replay (ordered before P4 atomics
        // by barriers 1..3)
        if (b == NCHAIN - 1) {
            reinterpret_cast<float4*>(g_ctx)[t] = make_float4(0.f, 0.f, 0.f, 0.f);
        }

        const float4* p[3];
        const float4* vv[3];
        float bias[3];
        float* outp[3];
#pragma unroll
        for (int k = 0; k < 3; k++) {
            int r = gw + k * nwarp;              // 6144 = 3 * 2048 exact
            if (r < 3 * H) {
                p[k] = reinterpret_cast<const float4*>(w_ih + (long)r * H);
                vv[k] = sbuf4; bias[k] = b_ih[r]; outp[k] = &g_gi[r];
            } else {
                int rr = r - 3 * H;
                p[k] = reinterpret_cast<const float4*>(w_hh + (long)rr * H);
                vv[k] = sbuf4 + 256; bias[k] = b_hh[rr]; outp[k] = &g_gh[rr];
            }
        }
        float a0 = 0.f, a1 = 0.f, a2 = 0.f;
#pragma unroll
        for (int it = 0; it < 8; it++) {
            float4 w0 = p[0][it * 32 + lane];
            float4 w1 = p[1][it * 32 + lane];
            float4 w2 = p[2][it * 32 + lane];
            float4 c0 = vv[0][it * 32 + lane];
            float4 c1 = vv[1][it * 32 + lane];
            float4 c2 = vv[2][it * 32 + lane];
            a0 += w0.x * c0.x + w0.y * c0.y + w0.z * c0.z + w0.w * c0.w;
            a1 += w1.x * c1.x + w1.y * c1.y + w1.z * c1.z + w1.w * c1.w;
            a2 += w2.x * c2.x + w2.y * c2.y + w2.z * c2.z + w2.w * c2.w;
        }
        a0 = warp_sum(a0); a1 = warp_sum(a1); a2 = warp_sum(a2);
        if (!lane) { *outp[0] = a0 + bias[0]; *outp[1] = a1 + bias[1]; *outp[2] = a2 + bias[2]; }
    }
    chain_sync();   // B1

    // ===== P2 (blocks 0..63): local GRU -> smem h ; v partials
    if (b < 64) {
#pragma unroll
        for (int k = 0; k < 4; k++) {
            int i = t + NT * k;
            float hp = ((const float*)(sbuf4 + 256))[i];   // h_prev still in shared
            float r = 1.f / (1.f + expf(-(g_gi[i] + g_gh[i])));
            float z = 1.f / (1.f + expf(-(g_gi[H + i] + g_gh[H + i])));
            float n = tanhf(g_gi[2 * H + i] + r * g_gh[2 * H + i]);
            float h = (1.f - z) * n + z * hp;
            h_sh[i] = h;                                    // overwrites x (done)
            if (b == 0) { g_h[i] = h; dout[V + i] = h; }    // hidden output + publish
        }
        __syncthreads();

        int jc = b >> 2;                          // 16 chunks of 64 rows
        int c = (b & 3) * NT + t;
        const float* base = attn_w + (long)(jc * 64) * H + c;
        float s = 0.f;
#pragma unroll 8
        for (int j = 0; j < 64; j++)
            s += base[(long)j * H] * h_sh[jc * 64 + j];
        g_vpart[jc][c] = s;
    }
    chain_sync();   // B2

    // ===== P3: local vred (all blocks) -> smem v ; scores 2 rows/warp interleaved
    {
        float4 acc = make_float4(0.f, 0.f, 0.f, 0.f);
#pragma unroll
        for (int j = 0; j < 16; j++) {
            float4 pv = reinterpret_cast<const float4*>(g_vpart[j])[t];
            acc.x += pv.x; acc.y += pv.y; acc.z += pv.z; acc.w += pv.w;
        }
        sbuf4[256 + t] = acc;                     // v replaces h_prev
        __syncthreads();

        const float4* e0 = reinterpret_cast<const float4*>(enc + (long)gw * H);
        const float4* e1 = reinterpret_cast<const float4*>(enc + (long)(gw + nwarp) * H);
        float a0 = 0.f, a1 = 0.f;
#pragma unroll
        for (int it = 0; it < 8; it++) {
            float4 x0 = e0[it * 32 + lane];
            float4 x1 = e1[it * 32 + lane];
            float4 vv = sbuf4[256 + it * 32 + lane];
            a0 += x0.x * vv.x + x0.y * vv.y + x0.z * vv.z + x0.w * vv.w;
            a1 += x1.x * vv.x + x1.y * vv.y + x1.z * vv.z + x1.w * vv.w;
        }
        a0 = warp_sum(a0); a1 = warp_sum(a1);
        if (!lane) { g_scores[gw] = a0; g_scores[gw + nwarp] = a1; }
        // attn_b is a constant pre-softmax shift -> softmax-invariant, dropped
    }
    chain_sync();   // B3

    // ===== P4: local softmax stats ; ctx partials -> atomicAdd(g_ctx)
    {
        float e_loc[16];
        float x[16];
        float m = -INFINITY;
#pragma unroll
        for (int k = 0; k < 16; k++) {
            x[k] = g_scores[t + NT * k];
            m = fmaxf(m, x[k]);
        }
#pragma unroll
        for (int o = 16; o; o >>= 1) m = fmaxf(m, __shfl_xor_sync(0xffffffffu, m, o));
        if (!lane) red[warp] = m;
        __syncthreads();
        if (warp == 0) {
            m = (lane < 8) ? red[lane] : -INFINITY;
#pragma unroll
            for (int o = 4; o; o >>= 1) m = fmaxf(m, __shfl_xor_sync(0xffffffffu, m, o));
            if (!lane) bcm = m;
        }
        __syncthreads();
        m = bcm;
        float sum = 0.f;
#pragma unroll
        for (int k = 0; k < 16; k++) { e_loc[k] = expf(x[k] - m); sum += e_loc[k]; }
        sum = warp_sum(sum);
        __syncthreads();
        if (!lane) red[warp] = sum;
        __syncthreads();
        if (warp == 0) {
            sum = (lane < 8) ? red[lane] : 0.f;
#pragma unroll
            for (int o = 4; o; o >>= 1) sum += __shfl_xor_sync(0xffffffffu, sum, o);
            if (!lane) bcs = sum;
        }
        __syncthreads();
        const float inv = 1.f / bcs;

        if (b == 0) {                             // attn_weights output
#pragma unroll
            for (int k = 0; k < 16; k++)
                dout[V + H + t + NT * k] = e_loc[k] * inv;
        }

        // ctx partial: block b -> rows [sc*64, sc*64+64), cols (b&3)*256+t
        const int sc = b >> 2;                    // 64 chunks of 64 rows
        const int c = (b & 3) * NT + t;
#pragma unroll
        for (int k = 0; k < 16; k++) {
            int s = t + NT * k;
            int j = s - sc * 64;
            if (j >= 0 && j < 64) w_sh[j] = e_loc[k] * inv;
        }
        __syncthreads();

        const float* base = enc + (long)(sc * 64) * H + c;   // L2-hot after scores
        float acc = 0.f;
#pragma unroll 8
        for (int s = 0; s < 64; s++)
            acc += w_sh[s] * base[(long)s * H];
        atomicAdd(&g_ctx[c], acc);                // 64 adds/address, spread
    }
    // kernel end publishes g_h / g_ctx to k_logits (griddepcontrol.wait joins)
}

// ================= K2: logits (flat, PDL secondary; L2 prefetch pre-join) =====
__global__ void k_logits(const float* __restrict__ out_w,
                         const float* __restrict__ out_b,
                         float* __restrict__ dout) {
    __shared__ float4 cat[512];  // [h | ctx]
    int t = threadIdx.x;
    int warp = t >> 5, lane = t & 31;
    int r = blockIdx.x * 8 + warp;

    // Pre-join: prefetch this block's 8 rows (64KB) of out_w into L2 while
    // k_chain is still running. Independent of chain outputs -> legal pre-wait.
    if (r < V) {
        const char* base = (const char*)(out_w + (long)r * (2 * H));
#pragma unroll
        for (int i = 0; i < 2; i++) {
            asm volatile("prefetch.global.L2 [%0];" ::
                         "l"(base + (lane + i * 32) * 256));
        }
    }

    // Join: wait for k_chain completion + memory visibility.
    asm volatile("griddepcontrol.wait;" ::: "memory");

    cat[t] = reinterpret_cast<const float4*>(g_h)[t];
    cat[256 + t] = reinterpret_cast<const float4*>(g_ctx)[t];
    __syncthreads();

    if (r >= V) return;
    const float4* wr = reinterpret_cast<const float4*>(out_w + (long)r * (2 * H));
    float acc = 0.f;
#pragma unroll
    for (int it = 0; it < 16; it++) {
        float4 w = wr[it * 32 + lane];
        float4 c = cat[it * 32 + lane];
        acc += w.x * c.x + w.y * c.y + w.z * c.z + w.w * c.w;
    }
    acc = warp_sum(acc);
    if (!lane) dout[r] = acc + out_b[r];
}

// ---------------- launch ----------------
extern "C" void kernel_launch(void* const* d_in, const int* in_sizes, int n_in,
                              void* d_out, int out_size) {
    const int* word = (const int*)d_in[0];
    const float* last_hidden = (const float*)d_in[1];
    const float* enc = (const float*)d_in[2];
    const float* emb = (const float*)d_in[3];
    const float* w_ih = (const float*)d_in[4];
    const float* w_hh = (const float*)d_in[5];
    const float* b_ih = (const float*)d_in[6];
    const float* b_hh = (const float*)d_in[7];
    const float* attn_w = (const float*)d_in[8];
    // d_in[9] = attn_b : constant pre-softmax shift -> softmax-invariant, dropped
    const float* out_w = (const float*)d_in[10];
    const float* out_b = (const float*)d_in[11];
    float* dout = (float*)d_out;

    k_chain<<<NCHAIN, NT>>>(word, last_hidden, enc, emb, w_ih, w_hh, b_ih, b_hh,
                            attn_w, dout);

    // PDL secondary: may begin (prefetch phase) while k_chain runs.
    cudaLaunchConfig_t cfg = {};
    cfg.gridDim = dim3((V + 7) / 8, 1, 1);
    cfg.blockDim = dim3(NT, 1, 1);
    cudaLaunchAttribute attr[1];
    attr[0].id = cudaLaunchAttributeProgrammaticStreamSerialization;
    attr[0].val.programmaticStreamSerializationAllowed = 1;
    cfg.attrs = attr;
    cfg.numAttrs = 1;
    cudaLaunchKernelEx(&cfg, k_logits, out_w, out_b, dout);
}

// round 17
// speedup vs baseline: 1.0595x; 1.0595x over previous
#include <cuda_runtime.h>
#include <math.h>

#define H 1024
#define V 50257
#define S 4096
#define NT 256
#define NCHAIN 256      // co-resident (2/SM); barriers count these

// ---------------- scratch (__device__ globals) ----------------
__device__ float g_gi[3 * H];
__device__ float g_gh[3 * H];
__device__ float g_h[H];
__device__ float g_v[H];             // accumulated via atomicAdd in P2
__device__ float g_scores[S];
__device__ float g_ctx[H];           // accumulated via atomicAdd in P4
__device__ unsigned g_cnt = 0;
__device__ unsigned g_gen = 0;

// ---------------- helpers ----------------
__device__ __forceinline__ float warp_sum(float v) {
#pragma unroll
    for (int o = 16; o; o >>= 1) v += __shfl_xor_sync(0xffffffffu, v, o);
    return v;
}

__device__ __forceinline__ void chain_sync() {
    __syncthreads();
    if (threadIdx.x == 0) {
        __threadfence();
        unsigned gen = *(volatile unsigned*)&g_gen;
        if (atomicAdd(&g_cnt, 1u) == NCHAIN - 1) {
            g_cnt = 0;
            __threadfence();
            *(volatile unsigned*)&g_gen = gen + 1;
        } else {
            while (*(volatile unsigned*)&g_gen == gen) { }
        }
        __threadfence();
    }
    __syncthreads();
}

// ================= K1: chain (persistent 256 blocks, 3 barriers) ==============
__global__ void __launch_bounds__(NT, 2)
k_chain(const int* __restrict__ word,
        const float* __restrict__ last_hidden,
        const float* __restrict__ enc,
        const float* __restrict__ emb,
        const float* __restrict__ w_ih,
        const float* __restrict__ w_hh,
        const float* __restrict__ b_ih,
        const float* __restrict__ b_hh,
        const float* __restrict__ attn_w,
        float* __restrict__ dout) {
    __shared__ float4 sbuf4[512];   // [0..255]: x then h ; [256..511]: h_prev then v
    __shared__ float red[8];
    __shared__ float bcm, bcs;
    __shared__ float w_sh[64];
    float* h_sh = (float*)sbuf4;

    const int t = threadIdx.x;
    const int b = blockIdx.x;
    const int warp = t >> 5, lane = t & 31;
    const int nwarp = NCHAIN * (NT / 32);        // 2048
    const int gw = b * (NT / 32) + warp;

    // ===== P1: gates — 3 rows per warp, loads interleaved (MLP=3)
    {
        const float* x = emb + (long)word[0] * H;
        sbuf4[t]       = reinterpret_cast<const float4*>(x)[t];
        sbuf4[256 + t] = reinterpret_cast<const float4*>(last_hidden)[t];
        __syncthreads();

        // zero the atomic accumulators for this replay (ordered before the
        // P2/P4 adds by barriers B1/B3)
        if (b == NCHAIN - 1)
            reinterpret_cast<float4*>(g_ctx)[t] = make_float4(0.f, 0.f, 0.f, 0.f);
        if (b == NCHAIN - 2)
            reinterpret_cast<float4*>(g_v)[t] = make_float4(0.f, 0.f, 0.f, 0.f);

        const float4* p[3];
        const float4* vv[3];
        float bias[3];
        float* outp[3];
#pragma unroll
        for (int k = 0; k < 3; k++) {
            int r = gw + k * nwarp;              // 6144 = 3 * 2048 exact
            if (r < 3 * H) {
                p[k] = reinterpret_cast<const float4*>(w_ih + (long)r * H);
                vv[k] = sbuf4; bias[k] = b_ih[r]; outp[k] = &g_gi[r];
            } else {
                int rr = r - 3 * H;
                p[k] = reinterpret_cast<const float4*>(w_hh + (long)rr * H);
                vv[k] = sbuf4 + 256; bias[k] = b_hh[rr]; outp[k] = &g_gh[rr];
            }
        }
        float a0 = 0.f, a1 = 0.f, a2 = 0.f;
#pragma unroll
        for (int it = 0; it < 8; it++) {
            float4 w0 = p[0][it * 32 + lane];
            float4 w1 = p[1][it * 32 + lane];
            float4 w2 = p[2][it * 32 + lane];
            float4 c0 = vv[0][it * 32 + lane];
            float4 c1 = vv[1][it * 32 + lane];
            float4 c2 = vv[2][it * 32 + lane];
            a0 += w0.x * c0.x + w0.y * c0.y + w0.z * c0.z + w0.w * c0.w;
            a1 += w1.x * c1.x + w1.y * c1.y + w1.z * c1.z + w1.w * c1.w;
            a2 += w2.x * c2.x + w2.y * c2.y + w2.z * c2.z + w2.w * c2.w;
        }
        a0 = warp_sum(a0); a1 = warp_sum(a1); a2 = warp_sum(a2);
        if (!lane) { *outp[0] = a0 + bias[0]; *outp[1] = a1 + bias[1]; *outp[2] = a2 + bias[2]; }
    }
    chain_sync();   // B1

    // ===== P2 (blocks 0..63): local GRU -> smem h ; vpart -> atomicAdd(g_v)
    //        (blocks 64..255): prefetch enc into L2 for P3/P4
    if (b < 64) {
#pragma unroll
        for (int k = 0; k < 4; k++) {
            int i = t + NT * k;
            float hp = ((const float*)(sbuf4 + 256))[i];   // h_prev still in shared
            float r = 1.f / (1.f + expf(-(g_gi[i] + g_gh[i])));
            float z = 1.f / (1.f + expf(-(g_gi[H + i] + g_gh[H + i])));
            float n = tanhf(g_gi[2 * H + i] + r * g_gh[2 * H + i]);
            float h = (1.f - z) * n + z * hp;
            h_sh[i] = h;                                    // overwrites x (done)
            if (b == 0) { g_h[i] = h; dout[V + i] = h; }    // hidden output + publish
        }
        __syncthreads();

        int jc = b >> 2;                          // 16 chunks of 64 rows
        int c = (b & 3) * NT + t;
        const float* base = attn_w + (long)(jc * 64) * H + c;
        float s = 0.f;
#pragma unroll 8
        for (int j = 0; j < 64; j++)
            s += base[(long)j * H] * h_sh[jc * 64 + j];
        atomicAdd(&g_v[c], s);                    // 16 adds/address, spread
    } else {
        // warm L2 with enc (16MB = 131072 lines of 128B; 192 blocks)
        unsigned u = (unsigned)(b - 64) * NT + t; // 0 .. 49151
        const char* eb = (const char*)enc;
#pragma unroll
        for (int k = 0; k < 3; k++) {
            unsigned line = u + k * 49152u;
            if (line < 131072u)
                asm volatile("prefetch.global.L2 [%0];" :: "l"(eb + (size_t)line * 128));
        }
    }
    chain_sync();   // B2

    // ===== P3: v from g_v (4KB, L2-hot) ; scores 2 rows/warp interleaved
    {
        sbuf4[256 + t] = reinterpret_cast<const float4*>(g_v)[t];
        __syncthreads();

        const float4* e0 = reinterpret_cast<const float4*>(enc + (long)gw * H);
        const float4* e1 = reinterpret_cast<const float4*>(enc + (long)(gw + nwarp) * H);
        float a0 = 0.f, a1 = 0.f;
#pragma unroll
        for (int it = 0; it < 8; it++) {
            float4 x0 = e0[it * 32 + lane];
            float4 x1 = e1[it * 32 + lane];
            float4 vv = sbuf4[256 + it * 32 + lane];
            a0 += x0.x * vv.x + x0.y * vv.y + x0.z * vv.z + x0.w * vv.w;
            a1 += x1.x * vv.x + x1.y * vv.y + x1.z * vv.z + x1.w * vv.w;
        }
        a0 = warp_sum(a0); a1 = warp_sum(a1);
        if (!lane) { g_scores[gw] = a0; g_scores[gw + nwarp] = a1; }
        // attn_b is a constant pre-softmax shift -> softmax-invariant, dropped
    }
    chain_sync();   // B3

    // ===== P4: local softmax stats ; ctx partials -> atomicAdd(g_ctx)
    {
        float e_loc[16];
        float x[16];
        float m = -INFINITY;
#pragma unroll
        for (int k = 0; k < 16; k++) {
            x[k] = g_scores[t + NT * k];
            m = fmaxf(m, x[k]);
        }
#pragma unroll
        for (int o = 16; o; o >>= 1) m = fmaxf(m, __shfl_xor_sync(0xffffffffu, m, o));
        if (!lane) red[warp] = m;
        __syncthreads();
        if (warp == 0) {
            m = (lane < 8) ? red[lane] : -INFINITY;
#pragma unroll
            for (int o = 4; o; o >>= 1) m = fmaxf(m, __shfl_xor_sync(0xffffffffu, m, o));
            if (!lane) bcm = m;
        }
        __syncthreads();
        m = bcm;
        float sum = 0.f;
#pragma unroll
        for (int k = 0; k < 16; k++) { e_loc[k] = expf(x[k] - m); sum += e_loc[k]; }
        sum = warp_sum(sum);
        __syncthreads();
        if (!lane) red[warp] = sum;
        __syncthreads();
        if (warp == 0) {
            sum = (lane < 8) ? red[lane] : 0.f;
#pragma unroll
            for (int o = 4; o; o >>= 1) sum += __shfl_xor_sync(0xffffffffu, sum, o);
            if (!lane) bcs = sum;
        }
        __syncthreads();
        const float inv = 1.f / bcs;

        if (b == 0) {                             // attn_weights output
#pragma unroll
            for (int k = 0; k < 16; k++)
                dout[V + H + t + NT * k] = e_loc[k] * inv;
        }

        // ctx partial: block b -> rows [sc*64, sc*64+64), cols (b&3)*256+t
        const int sc = b >> 2;                    // 64 chunks of 64 rows
        const int c = (b & 3) * NT + t;
#pragma unroll
        for (int k = 0; k < 16; k++) {
            int s = t + NT * k;
            int j = s - sc * 64;
            if (j >= 0 && j < 64) w_sh[j] = e_loc[k] * inv;
        }
        __syncthreads();

        const float* base = enc + (long)(sc * 64) * H + c;   // L2-hot
        float acc = 0.f;
#pragma unroll 8
        for (int s = 0; s < 64; s++)
            acc += w_sh[s] * base[(long)s * H];
        atomicAdd(&g_ctx[c], acc);                // 64 adds/address, spread
    }
    // kernel end publishes g_h / g_ctx to k_logits
}

// ================= K2: logits (flat; measured 6.66 TB/s — FROZEN) =============
__global__ void k_logits(const float* __restrict__ out_w,
                         const float* __restrict__ out_b,
                         float* __restrict__ dout) {
    __shared__ float4 cat[512];  // [h | ctx]
    int t = threadIdx.x;
    cat[t] = reinterpret_cast<const float4*>(g_h)[t];
    cat[256 + t] = reinterpret_cast<const float4*>(g_ctx)[t];
    __syncthreads();

    int warp = t >> 5, lane = t & 31;
    int r = blockIdx.x * 8 + warp;
    if (r >= V) return;
    const float4* wr = reinterpret_cast<const float4*>(out_w + (long)r * (2 * H));
    float acc = 0.f;
#pragma unroll
    for (int it = 0; it < 16; it++) {
        float4 w = wr[it * 32 + lane];
        float4 c = cat[it * 32 + lane];
        acc += w.x * c.x + w.y * c.y + w.z * c.z + w.w * c.w;
    }
    acc = warp_sum(acc);
    if (!lane) dout[r] = acc + out_b[r];
}

// ---------------- launch ----------------
extern "C" void kernel_launch(void* const* d_in, const int* in_sizes, int n_in,
                              void* d_out, int out_size) {
    const int* word = (const int*)d_in[0];
    const float* last_hidden = (const float*)d_in[1];
    const float* enc = (const float*)d_in[2];
    const float* emb = (const float*)d_in[3];
    const float* w_ih = (const float*)d_in[4];
    const float* w_hh = (const float*)d_in[5];
    const float* b_ih = (const float*)d_in[6];
    const float* b_hh = (const float*)d_in[7];
    const float* attn_w = (const float*)d_in[8];
    // d_in[9] = attn_b : constant pre-softmax shift -> softmax-invariant, dropped
    const float* out_w = (const float*)d_in[10];
    const float* out_b = (const float*)d_in[11];
    float* dout = (float*)d_out;

    k_chain<<<NCHAIN, NT>>>(word, last_hidden, enc, emb, w_ih, w_hh, b_ih, b_hh,
                            attn_w, dout);
    k_logits<<<(V + 7) / 8, NT>>>(out_w, out_b, dout);
}